// round 13
// baseline (speedup 1.0000x reference)
#include <cuda_runtime.h>
#include <cstdint>

// B=4, N=256, OBS=40, ACT=8, HEAD=8, DIM=32, T=256
// Algebra: nh/hid independent of broadcast index -> only column sums S_n,S_h;
// final gather at tgt -> ah needed at 4 rows only.
// fp32 SIMT GEMMs: BM=BN=BK=32, 64-thread blocks, 4x4 microtile (16 FFMA/2 LDS),
// cp.async for pure operands (A pre-transposed to [k][m]), LDG-staging for
// operands needing fused arithmetic (split-K adds, relu+bias). 512-block grids.

__device__ float g_E1T[256 * 1024];     // E1 transposed [t][m]
__device__ float g_adjT[256 * 256];     // adj transposed [n][i]
__device__ float g_E2p[2 * 1024 * 256]; // E2 split-K partials [ks][m][t]
__device__ float g_NEpT[2 * 256 * 1024];// NE split-K partials transposed [ks][t][m]
__device__ float g_Sn[1024], g_Sh[1024], g_AH[1024];

#define KS_OFF 262144

__device__ __forceinline__ void cp16(uint32_t dst, const void* src) {
    asm volatile("cp.async.ca.shared.global [%0], [%1], 16;\n" :: "r"(dst), "l"(src));
}
#define CP_COMMIT() asm volatile("cp.async.commit_group;\n" ::)
#define CP_WAIT0()  asm volatile("cp.async.wait_group 0;\n" ::)

// copy one (kr,half) slice: 16 floats as 4x 16B
#define CP4(dstB, srcP)                                                        \
    { cp16((dstB), (srcP)); cp16((dstB) + 16, (srcP) + 4);                     \
      cp16((dstB) + 32, (srcP) + 8); cp16((dstB) + 48, (srcP) + 12); }

#define COMP(As_, Bs_)                                                         \
    _Pragma("unroll")                                                          \
    for (int kk = 0; kk < 32; kk++) {                                          \
        float4 av = *(const float4*)&As_[kk][ty * 4];                          \
        float4 bv = *(const float4*)&Bs_[kk][tx * 4];                          \
        acc[0][0] += av.x * bv.x; acc[0][1] += av.x * bv.y;                    \
        acc[0][2] += av.x * bv.z; acc[0][3] += av.x * bv.w;                    \
        acc[1][0] += av.y * bv.x; acc[1][1] += av.y * bv.y;                    \
        acc[1][2] += av.y * bv.z; acc[1][3] += av.y * bv.w;                    \
        acc[2][0] += av.z * bv.x; acc[2][1] += av.z * bv.y;                    \
        acc[2][2] += av.z * bv.z; acc[2][3] += av.z * bv.w;                    \
        acc[3][0] += av.w * bv.x; acc[3][1] += av.w * bv.y;                    \
        acc[3][2] += av.w * bv.z; acc[3][3] += av.w * bv.w;                    \
    }

// ---------------------------------------------------------------------------
// K1: E1T = relu(obs@We1+be1)^T. Block 0 zeroes the accumulators.
__global__ void k_embed1(const float* __restrict__ x, const float* __restrict__ We1,
                         const float* __restrict__ be1) {
    __shared__ float xs[4][40];
    int r0 = blockIdx.x * 4;
    int tid = threadIdx.x;
    if (blockIdx.x == 0) {
#pragma unroll
        for (int i = 0; i < 4; i++) {
            g_Sn[i * 256 + tid] = 0.f;
            g_Sh[i * 256 + tid] = 0.f;
            g_AH[i * 256 + tid] = 0.f;
        }
    }
    if (tid < 160) {
        int rr = tid / 40, k = tid % 40;
        int row = r0 + rr;
        int b = row >> 8, i = row & 255;
        xs[rr][k] = x[b * 257 * 40 + i * 40 + k];
    }
    __syncthreads();
    float bias = be1[tid];
    float acc[4] = {bias, bias, bias, bias};
#pragma unroll
    for (int k = 0; k < 40; k++) {
        float w = We1[k * 256 + tid];
#pragma unroll
        for (int rr = 0; rr < 4; rr++) acc[rr] += xs[rr][k] * w;
    }
    *(float4*)(g_E1T + (size_t)tid * 1024 + r0) =
        make_float4(fmaxf(acc[0], 0.f), fmaxf(acc[1], 0.f),
                    fmaxf(acc[2], 0.f), fmaxf(acc[3], 0.f));
}

// ---------------------------------------------------------------------------
// adjT[n][i] = adj[i][n]. grid (8,8), block (32,8).
__global__ void k_prep(const float* __restrict__ adj) {
    __shared__ float ts[32][33];
    int tx = threadIdx.x, ty = threadIdx.y;
    int i0 = blockIdx.x * 32, n0 = blockIdx.y * 32;
    for (int r = ty; r < 32; r += 8)
        ts[r][tx] = adj[(size_t)(i0 + r) * 256 + n0 + tx];
    __syncthreads();
    for (int r = ty; r < 32; r += 8)
        g_adjT[(size_t)(n0 + r) * 256 + i0 + tx] = ts[tx][r];
}

// ---------------------------------------------------------------------------
// K2: E2p[ks] = E1[:,kb:kb+128] @ We2[kb:kb+128,:]. grid (8,32,2), 64 thr.
// Both operands via cp.async (A from E1T).
__global__ void __launch_bounds__(64) k_gemmE2(const float* __restrict__ We2) {
    __shared__ float As[2][32][32];
    __shared__ float Bs[2][32][32];
    int tid = threadIdx.x, tx = tid & 7, ty = tid >> 3;
    int kr = tid >> 1, half = tid & 1;
    int t0 = blockIdx.x * 32, m0 = blockIdx.y * 32, kb = blockIdx.z * 128;
    const float* aS = g_E1T + (size_t)(kb + kr) * 1024 + m0 + half * 16;
    const float* bS = We2 + (size_t)(kb + kr) * 256 + t0 + half * 16;
    uint32_t aB = (uint32_t)__cvta_generic_to_shared(&As[0][0][0]) +
                  (uint32_t)(kr * 32 + half * 16) * 4;
    uint32_t bB = (uint32_t)__cvta_generic_to_shared(&Bs[0][0][0]) +
                  (uint32_t)(kr * 32 + half * 16) * 4;

#define LDE2(c, st)                                                            \
    { CP4(aB + (st) * 4096, aS + (size_t)(c) * 32 * 1024);                     \
      CP4(bB + (st) * 4096, bS + (size_t)(c) * 32 * 256); CP_COMMIT(); }

    LDE2(0, 0)
    CP_WAIT0(); __syncthreads();
    float acc[4][4] = {};
    for (int c = 0; c < 4; c++) {
        if (c < 3) LDE2(c + 1, (c + 1) & 1)
        COMP(As[c & 1], Bs[c & 1])
        __syncthreads();
        if (c < 3) { CP_WAIT0(); __syncthreads(); }
    }
#undef LDE2
    float* o = g_E2p + (size_t)blockIdx.z * KS_OFF + (size_t)m0 * 256 + t0;
#pragma unroll
    for (int i = 0; i < 4; i++)
        *(float4*)(o + (size_t)(ty * 4 + i) * 256 + tx * 4) =
            make_float4(acc[i][0], acc[i][1], acc[i][2], acc[i][3]);
}

// ---------------------------------------------------------------------------
// K3: NEpT[ks][t][b*256+i] = (adj[:,kb:+128] @ relu(E2p0+E2p1+be2)[kb:+128,:])^T
// grid (8 t, 8 i, 8 z=b*2+ks), 64 thr. A via cp.async (adjT), B via LDG-staging.
__global__ void __launch_bounds__(64) k_gemmNE(const float* __restrict__ be2) {
    __shared__ float As[2][32][32];
    __shared__ float Bs[2][32][32];
    __shared__ float smc[32][36];
    int tid = threadIdx.x, tx = tid & 7, ty = tid >> 3;
    int kr = tid >> 1, half = tid & 1;
    int t0 = blockIdx.x * 32, i0 = blockIdx.y * 32;
    int b = blockIdx.z >> 1, ks = blockIdx.z & 1, kb = ks * 128;
    const float* aS = g_adjT + (size_t)(kb + kr) * 256 + i0 + half * 16;
    size_t bBase = (size_t)(b * 256 + kb + kr) * 256 + t0 + half * 16;
    uint32_t aB = (uint32_t)__cvta_generic_to_shared(&As[0][0][0]) +
                  (uint32_t)(kr * 32 + half * 16) * 4;
    float4 bq[4];
#pragma unroll
    for (int q = 0; q < 4; q++) bq[q] = *(const float4*)(be2 + t0 + half * 16 + q * 4);

    float4 r[4];
#define LDA(c, st) { CP4(aB + (st) * 4096, aS + (size_t)(c) * 32 * 256); CP_COMMIT(); }
#define LDB(c)                                                                 \
    _Pragma("unroll")                                                          \
    for (int q = 0; q < 4; q++) {                                              \
        float4 e = *(const float4*)(g_E2p + bBase + (size_t)(c) * 8192 + q * 4);\
        float4 f = *(const float4*)(g_E2p + KS_OFF + bBase + (size_t)(c) * 8192 + q * 4);\
        r[q] = make_float4(fmaxf(e.x + f.x + bq[q].x, 0.f),                    \
                           fmaxf(e.y + f.y + bq[q].y, 0.f),                    \
                           fmaxf(e.z + f.z + bq[q].z, 0.f),                    \
                           fmaxf(e.w + f.w + bq[q].w, 0.f));                   \
    }
#define STB(st)                                                                \
    _Pragma("unroll")                                                          \
    for (int q = 0; q < 4; q++)                                                \
        *(float4*)&Bs[st][kr][half * 16 + q * 4] = r[q];

    LDA(0, 0) LDB(0)
    CP_WAIT0(); STB(0) __syncthreads();
    float acc[4][4] = {};
    for (int c = 0; c < 4; c++) {
        if (c < 3) { LDA(c + 1, (c + 1) & 1) LDB(c + 1) }
        COMP(As[c & 1], Bs[c & 1])
        __syncthreads();
        if (c < 3) { CP_WAIT0(); STB((c + 1) & 1) __syncthreads(); }
    }
#undef LDA
#undef LDB
#undef STB
    // transposed store via smem
#pragma unroll
    for (int i = 0; i < 4; i++)
        *(float4*)&smc[ty * 4 + i][tx * 4] =
            make_float4(acc[i][0], acc[i][1], acc[i][2], acc[i][3]);
    __syncthreads();
    int tr = tid >> 1, c0 = half * 16;
    float* o = g_NEpT + (size_t)ks * KS_OFF + (size_t)(t0 + tr) * 1024 + b * 256 + i0 + c0;
#pragma unroll
    for (int q = 0; q < 4; q++)
        *(float4*)(o + q * 4) =
            make_float4(smc[c0 + q * 4 + 0][tr], smc[c0 + q * 4 + 1][tr],
                        smc[c0 + q * 4 + 2][tr], smc[c0 + q * 4 + 3][tr]);
}

// ---------------------------------------------------------------------------
// K4: column sums of relu((NEpT0+NEpT1)^T @ W + bias). grid (8 n, 32 m, 2 which).
// A via LDG-staging (partial add), B (weights) via cp.async.
__global__ void __launch_bounds__(64) k_colsum(const float* __restrict__ Wn,
                                               const float* __restrict__ bn,
                                               const float* __restrict__ Wh,
                                               const float* __restrict__ bh) {
    __shared__ float As[2][32][32];
    __shared__ float Bs[2][32][32];
    __shared__ float red[32];
    const float* W = blockIdx.z ? Wh : Wn;
    const float* bias = blockIdx.z ? bh : bn;
    float* S = blockIdx.z ? g_Sh : g_Sn;
    int tid = threadIdx.x, tx = tid & 7, ty = tid >> 3;
    int kr = tid >> 1, half = tid & 1;
    int n0 = blockIdx.x * 32, m0 = blockIdx.y * 32;
    int batch = m0 >> 8;
    size_t aBase = (size_t)kr * 1024 + m0 + half * 16;
    const float* bS = W + (size_t)kr * 256 + n0 + half * 16;
    uint32_t bB = (uint32_t)__cvta_generic_to_shared(&Bs[0][0][0]) +
                  (uint32_t)(kr * 32 + half * 16) * 4;

    float4 r[4];
#define LDBW(c, st) { CP4(bB + (st) * 4096, bS + (size_t)(c) * 32 * 256); CP_COMMIT(); }
#define LDAP(c)                                                                \
    _Pragma("unroll")                                                          \
    for (int q = 0; q < 4; q++) {                                              \
        float4 u = *(const float4*)(g_NEpT + aBase + (size_t)(c) * 32768 + q * 4);\
        float4 v = *(const float4*)(g_NEpT + KS_OFF + aBase + (size_t)(c) * 32768 + q * 4);\
        r[q] = make_float4(u.x + v.x, u.y + v.y, u.z + v.z, u.w + v.w);        \
    }
#define STA(st)                                                                \
    _Pragma("unroll")                                                          \
    for (int q = 0; q < 4; q++)                                                \
        *(float4*)&As[st][kr][half * 16 + q * 4] = r[q];

    LDBW(0, 0) LDAP(0)
    CP_WAIT0(); STA(0) __syncthreads();
    float acc[4][4] = {};
    for (int c = 0; c < 8; c++) {
        if (c < 7) { LDBW(c + 1, (c + 1) & 1) LDAP(c + 1) }
        COMP(As[c & 1], Bs[c & 1])
        __syncthreads();
        if (c < 7) { CP_WAIT0(); STA((c + 1) & 1) __syncthreads(); }
    }
#undef LDBW
#undef LDAP
#undef STA
    if (tid < 32) red[tid] = 0.f;
    __syncthreads();
    float4 bi = *(const float4*)(bias + n0 + tx * 4);
    float ba4[4] = {bi.x, bi.y, bi.z, bi.w};
#pragma unroll
    for (int j = 0; j < 4; j++) {
        float s = fmaxf(acc[0][j] + ba4[j], 0.f) + fmaxf(acc[1][j] + ba4[j], 0.f) +
                  fmaxf(acc[2][j] + ba4[j], 0.f) + fmaxf(acc[3][j] + ba4[j], 0.f);
        atomicAdd(&red[tx * 4 + j], s);
    }
    __syncthreads();
    if (tid < 32) atomicAdd(&S[batch * 256 + n0 + tid], red[tid]);
}

// ---------------------------------------------------------------------------
// ah split-K partials from E2p. grid 16 (4b x 4 ksegs of 64), 256 thr.
__global__ void k_ah(const float* __restrict__ x, const float* __restrict__ Wl,
                     const float* __restrict__ be2) {
    __shared__ float vs[64];
    int b = blockIdx.x >> 2, kseg = blockIdx.x & 3;
    int t = threadIdx.x;
    int tgt = (int)x[b * 257 * 40 + 256 * 40];
    if (t < 64) {
        int col = kseg * 64 + t;
        size_t idx = (size_t)(b * 256 + tgt) * 256 + col;
        vs[t] = fmaxf(g_E2p[idx] + g_E2p[KS_OFF + idx] + be2[col], 0.f);
    }
    __syncthreads();
    float acc = 0.f;
#pragma unroll 8
    for (int k = 0; k < 64; k++)
        acc += vs[k] * Wl[(kseg * 64 + k) * 256 + t];
    atomicAdd(&g_AH[b * 256 + t], acc);
}

// ---------------------------------------------------------------------------
__global__ void k_final(const float* __restrict__ bl, const float* __restrict__ Wa,
                        const float* __restrict__ ba, float* __restrict__ out) {
    __shared__ float od[32];
    int b = blockIdx.x, tid = threadIdx.x;
    int h = tid >> 5, d = tid & 31;
    int t = d * 8 + h;
    float ahv = fmaxf(g_AH[b * 256 + t] + bl[t], 0.f);
    float logit = ahv * g_Sn[b * 256 + t];
    float m = logit;
#pragma unroll
    for (int o = 16; o > 0; o >>= 1) m = fmaxf(m, __shfl_xor_sync(0xffffffffu, m, o));
    float e = expf(logit - m);
    float ssum = e;
#pragma unroll
    for (int o = 16; o > 0; o >>= 1) ssum += __shfl_xor_sync(0xffffffffu, ssum, o);
    float val = (e / ssum) * g_Sh[b * 256 + t] * 0.125f;
    if (tid < 32) od[tid] = 0.f;
    __syncthreads();
    atomicAdd(&od[d], val);
    __syncthreads();
    if (tid < 8) {
        float acc = ba[tid];
#pragma unroll
        for (int dd = 0; dd < 32; dd++) acc += od[dd] * Wa[dd * 8 + tid];
        out[b * 8 + tid] = acc;
    }
    (void)h;
}

// ---------------------------------------------------------------------------
extern "C" void kernel_launch(void* const* d_in, const int* in_sizes, int n_in,
                              void* d_out, int out_size) {
    const float* x   = (const float*)d_in[0];
    const float* adj = (const float*)d_in[1];
    const float* We1 = (const float*)d_in[2];
    const float* be1 = (const float*)d_in[3];
    const float* We2 = (const float*)d_in[4];
    const float* be2 = (const float*)d_in[5];
    const float* Wl  = (const float*)d_in[6];
    const float* bl  = (const float*)d_in[7];
    const float* Wn  = (const float*)d_in[8];
    const float* bn  = (const float*)d_in[9];
    const float* Wh  = (const float*)d_in[10];
    const float* bh  = (const float*)d_in[11];
    const float* Wa  = (const float*)d_in[12];
    const float* ba  = (const float*)d_in[13];
    float* out = (float*)d_out;

    k_embed1<<<256, 256>>>(x, We1, be1);
    k_prep<<<dim3(8, 8), dim3(32, 8)>>>(adj);
    k_gemmE2<<<dim3(8, 32, 2), 64>>>(We2);
    k_gemmNE<<<dim3(8, 8, 8), 64>>>(be2);
    k_colsum<<<dim3(8, 32, 2), 64>>>(Wn, bn, Wh, bh);
    k_ah<<<16, 256>>>(x, Wl, be2);
    k_final<<<4, 256>>>(bl, Wa, ba, out);

    (void)in_sizes; (void)n_in; (void)out_size;
}

// round 15
// speedup vs baseline: 1.2479x; 1.2479x over previous
#include <cuda_runtime.h>
#include <cstdint>

// B=4, N=256, OBS=40, ACT=8, HEAD=8, DIM=32, T=256
// Algebra: nh/hid independent of broadcast index -> only column sums S_n,S_h (B,T);
// final gather at tgt -> ah needed at 4 rows only.
// Split-K=2 (atomic-free): producers write two partial buffers; consumers add at load.
// GEMMs: BM=64 BN=32 BK=16, 128 threads, microtile 2 m-pairs x 4 n via PACKED
// fma.rn.f32x2 (8 FFMA2 = 16 MACs per kk), register-prefetch double-buffered smem.

__device__ float g_E1[1024 * 256];
__device__ float g_E2[2 * 1024 * 256];   // [ksplit][row][col] partials of E1@We2
__device__ float g_NE[2 * 1024 * 256];   // [ksplit][b*256+i][col] partials of adj@relu_E2
__device__ float g_Sn[1024];
__device__ float g_Sh[1024];
__device__ float g_AH[1024];

#define E2_HALF (1024 * 256)

typedef unsigned long long u64;
__device__ __forceinline__ void fma2(u64& d, u64 a, u64 b) {
    asm("fma.rn.f32x2 %0, %1, %2, %0;" : "+l"(d) : "l"(a), "l"(b));
}
__device__ __forceinline__ u64 dup2f(float v) {
    u64 r; asm("mov.b64 %0, {%1, %1};" : "=l"(r) : "f"(v)); return r;
}
__device__ __forceinline__ void unpk(u64 v, float& lo, float& hi) {
    asm("mov.b64 {%0, %1}, %2;" : "=f"(lo), "=f"(hi) : "l"(v));
}

// ---------------------------------------------------------------------------
// K1: E1 = relu(obs @ We1 + be1); block 0 also zeroes the accumulators.
__global__ void k_embed1(const float* __restrict__ x, const float* __restrict__ We1,
                         const float* __restrict__ be1) {
    __shared__ float xs[4][40];
    int r0 = blockIdx.x * 4;
    int tid = threadIdx.x;
    if (blockIdx.x == 0) {
#pragma unroll
        for (int i = 0; i < 4; i++) {
            g_Sn[i * 256 + tid] = 0.f;
            g_Sh[i * 256 + tid] = 0.f;
            g_AH[i * 256 + tid] = 0.f;
        }
    }
    if (tid < 160) {
        int rr = tid / 40, k = tid % 40;
        int row = r0 + rr;
        int b = row >> 8, i = row & 255;
        xs[rr][k] = x[b * 257 * 40 + i * 40 + k];
    }
    __syncthreads();
    float bias = be1[tid];
    float acc[4] = {bias, bias, bias, bias};
#pragma unroll
    for (int k = 0; k < 40; k++) {
        float w = We1[k * 256 + tid];
#pragma unroll
        for (int rr = 0; rr < 4; rr++) acc[rr] += xs[rr][k] * w;
    }
#pragma unroll
    for (int rr = 0; rr < 4; rr++)
        g_E1[(r0 + rr) * 256 + tid] = fmaxf(acc[rr], 0.f);
}

// ---------------------------------------------------------------------------
// Tiling: BM=64 BN=32 BK=16, 128 threads.
// A loader: arow=tid>>1 (0..63), akq=tid&1 -> float4 at k = akq*4 and 8+akq*4,
//           stored transposed into As[k][m] (pad 68).
// B loader: brow=tid>>3 (0..15), bq=tid&7 -> float4 at n = bq*4 into Bs[k][n].
// Compute:  tx=tid&7 (cols tx*4), ty=tid>>3 (rows ty*4..ty*4+3),
//           acc2[p][j] = packed (m=ty*4+2p, ty*4+2p+1) x (n=tx*4+j).

#define MT_COMPUTE(As_, Bs_)                                                   \
    _Pragma("unroll")                                                          \
    for (int kk = 0; kk < 16; kk++) {                                          \
        ulonglong2 ap = *(const ulonglong2*)&As_[kk][ty * 4];                  \
        float4 bv = *(const float4*)&Bs_[kk][tx * 4];                          \
        u64 d0 = dup2f(bv.x), d1 = dup2f(bv.y);                                \
        u64 d2 = dup2f(bv.z), d3 = dup2f(bv.w);                                \
        fma2(acc2[0][0], ap.x, d0); fma2(acc2[0][1], ap.x, d1);                \
        fma2(acc2[0][2], ap.x, d2); fma2(acc2[0][3], ap.x, d3);                \
        fma2(acc2[1][0], ap.y, d0); fma2(acc2[1][1], ap.y, d1);                \
        fma2(acc2[1][2], ap.y, d2); fma2(acc2[1][3], ap.y, d3);                \
    }

#define MT_UNPACK()                                                            \
    float acc[4][4];                                                           \
    _Pragma("unroll")                                                          \
    for (int p = 0; p < 2; p++)                                                \
        _Pragma("unroll")                                                      \
        for (int j = 0; j < 4; j++)                                            \
            unpk(acc2[p][j], acc[2 * p][j], acc[2 * p + 1][j]);

#define MT_STORE_A(dst, v0, v1)                                                \
    {                                                                          \
        dst[akq * 4 + 0][arow] = v0.x; dst[akq * 4 + 1][arow] = v0.y;          \
        dst[akq * 4 + 2][arow] = v0.z; dst[akq * 4 + 3][arow] = v0.w;          \
        dst[8 + akq * 4 + 0][arow] = v1.x; dst[8 + akq * 4 + 1][arow] = v1.y;  \
        dst[8 + akq * 4 + 2][arow] = v1.z; dst[8 + akq * 4 + 3][arow] = v1.w;  \
    }

// K2: E2 partial = E1 @ We2 over K-half z. grid (8,16,2), 128 thr.
__global__ void __launch_bounds__(128) k_gemmE2(const float* __restrict__ E1,
                                                const float* __restrict__ We2) {
    __shared__ float As[2][16][68];
    __shared__ float Bs[2][16][32];
    int tid = threadIdx.x;
    int tx = tid & 7, ty = tid >> 3;
    int arow = tid >> 1, akq = tid & 1;
    int brow = tid >> 3, bq = tid & 7;
    int row0 = blockIdx.y * 64, col0 = blockIdx.x * 32, kb = blockIdx.z * 128;
    const float* aptr = E1 + (row0 + arow) * 256 + kb + akq * 4;
    const float* bptr = We2 + (size_t)(kb + brow) * 256 + col0 + bq * 4;

    float4 a0 = *(const float4*)aptr;
    float4 a1 = *(const float4*)(aptr + 8);
    float4 b0 = *(const float4*)bptr;
    MT_STORE_A(As[0], a0, a1);
    *(float4*)&Bs[0][brow][bq * 4] = b0;
    __syncthreads();

    u64 acc2[2][4] = {};
    int s = 0;
    for (int k0 = 0; k0 < 128; k0 += 16) {
        if (k0 + 16 < 128) {
            a0 = *(const float4*)(aptr + k0 + 16);
            a1 = *(const float4*)(aptr + k0 + 24);
            b0 = *(const float4*)(bptr + (size_t)(k0 + 16) * 256);
        }
        MT_COMPUTE(As[s], Bs[s])
        if (k0 + 16 < 128) {
            int ns = s ^ 1;
            MT_STORE_A(As[ns], a0, a1);
            *(float4*)&Bs[ns][brow][bq * 4] = b0;
            __syncthreads();
            s = ns;
        }
    }
    MT_UNPACK()
    float* outp = g_E2 + (size_t)blockIdx.z * E2_HALF;
#pragma unroll
    for (int i = 0; i < 4; i++)
        *(float4*)(outp + (size_t)(row0 + ty * 4 + i) * 256 + col0 + tx * 4) =
            make_float4(acc[i][0], acc[i][1], acc[i][2], acc[i][3]);
}

// K3: NE partial = adj[:,kb:+128] @ relu(E2a+E2b+be2). z=b*2+ks. grid (8,4,8).
__global__ void __launch_bounds__(128) k_gemmNE(const float* __restrict__ adj,
                                                const float* __restrict__ be2) {
    __shared__ float As[2][16][68];
    __shared__ float Bs[2][16][32];
    int tid = threadIdx.x;
    int tx = tid & 7, ty = tid >> 3;
    int arow = tid >> 1, akq = tid & 1;
    int brow = tid >> 3, bq = tid & 7;
    int b = blockIdx.z >> 1, ks = blockIdx.z & 1, kb = ks * 128;
    int row0 = blockIdx.y * 64, col0 = blockIdx.x * 32;
    const float* aptr = adj + (row0 + arow) * 256 + kb + akq * 4;
    const float* pa = g_E2 + (size_t)(b * 256 + kb + brow) * 256 + col0 + bq * 4;
    const float* pb = pa + E2_HALF;
    float4 bi = *(const float4*)(be2 + col0 + bq * 4);

    float4 a0 = *(const float4*)aptr;
    float4 a1 = *(const float4*)(aptr + 8);
    float4 e0 = *(const float4*)pa;
    float4 f0 = *(const float4*)pb;
    MT_STORE_A(As[0], a0, a1);
    *(float4*)&Bs[0][brow][bq * 4] =
        make_float4(fmaxf(e0.x + f0.x + bi.x, 0.f), fmaxf(e0.y + f0.y + bi.y, 0.f),
                    fmaxf(e0.z + f0.z + bi.z, 0.f), fmaxf(e0.w + f0.w + bi.w, 0.f));
    __syncthreads();

    u64 acc2[2][4] = {};
    int s = 0;
    for (int k0 = 0; k0 < 128; k0 += 16) {
        if (k0 + 16 < 128) {
            a0 = *(const float4*)(aptr + k0 + 16);
            a1 = *(const float4*)(aptr + k0 + 24);
            e0 = *(const float4*)(pa + (size_t)(k0 + 16) * 256);
            f0 = *(const float4*)(pb + (size_t)(k0 + 16) * 256);
        }
        MT_COMPUTE(As[s], Bs[s])
        if (k0 + 16 < 128) {
            int ns = s ^ 1;
            MT_STORE_A(As[ns], a0, a1);
            *(float4*)&Bs[ns][brow][bq * 4] =
                make_float4(fmaxf(e0.x + f0.x + bi.x, 0.f), fmaxf(e0.y + f0.y + bi.y, 0.f),
                            fmaxf(e0.z + f0.z + bi.z, 0.f), fmaxf(e0.w + f0.w + bi.w, 0.f));
            __syncthreads();
            s = ns;
        }
    }
    MT_UNPACK()
    float* outp = g_NE + (size_t)ks * E2_HALF + (size_t)(b * 256) * 256;
#pragma unroll
    for (int i = 0; i < 4; i++)
        *(float4*)(outp + (size_t)(row0 + ty * 4 + i) * 256 + col0 + tx * 4) =
            make_float4(acc[i][0], acc[i][1], acc[i][2], acc[i][3]);
}

// K4: column sums of relu((NEa+NEb)@W + bias); z: 0->Wn/Sn, 1->Wh/Sh. grid (8,16,2).
__global__ void __launch_bounds__(128) k_colsum(const float* __restrict__ Wn,
                                                const float* __restrict__ bn,
                                                const float* __restrict__ Wh,
                                                const float* __restrict__ bh) {
    __shared__ float As[2][16][68];
    __shared__ float Bs[2][16][32];
    __shared__ float red[32];
    const float* W = blockIdx.z ? Wh : Wn;
    const float* bias = blockIdx.z ? bh : bn;
    float* S = blockIdx.z ? g_Sh : g_Sn;
    int tid = threadIdx.x;
    int tx = tid & 7, ty = tid >> 3;
    int arow = tid >> 1, akq = tid & 1;
    int brow = tid >> 3, bq = tid & 7;
    int row0 = blockIdx.y * 64, col0 = blockIdx.x * 32;
    int batch = blockIdx.y >> 2;
    const float* pa = g_NE + (size_t)(row0 + arow) * 256 + akq * 4;
    const float* pb = pa + E2_HALF;
    const float* bptr = W + (size_t)brow * 256 + col0 + bq * 4;

    float4 u0 = *(const float4*)pa, v0 = *(const float4*)pb;
    float4 u1 = *(const float4*)(pa + 8), v1 = *(const float4*)(pb + 8);
    float4 b0 = *(const float4*)bptr;
    float4 s0 = make_float4(u0.x + v0.x, u0.y + v0.y, u0.z + v0.z, u0.w + v0.w);
    float4 s1 = make_float4(u1.x + v1.x, u1.y + v1.y, u1.z + v1.z, u1.w + v1.w);
    MT_STORE_A(As[0], s0, s1);
    *(float4*)&Bs[0][brow][bq * 4] = b0;
    __syncthreads();

    u64 acc2[2][4] = {};
    int s = 0;
    for (int k0 = 0; k0 < 256; k0 += 16) {
        if (k0 + 16 < 256) {
            u0 = *(const float4*)(pa + k0 + 16);
            v0 = *(const float4*)(pb + k0 + 16);
            u1 = *(const float4*)(pa + k0 + 24);
            v1 = *(const float4*)(pb + k0 + 24);
            b0 = *(const float4*)(bptr + (size_t)(k0 + 16) * 256);
        }
        MT_COMPUTE(As[s], Bs[s])
        if (k0 + 16 < 256) {
            int ns = s ^ 1;
            s0 = make_float4(u0.x + v0.x, u0.y + v0.y, u0.z + v0.z, u0.w + v0.w);
            s1 = make_float4(u1.x + v1.x, u1.y + v1.y, u1.z + v1.z, u1.w + v1.w);
            MT_STORE_A(As[ns], s0, s1);
            *(float4*)&Bs[ns][brow][bq * 4] = b0;
            __syncthreads();
            s = ns;
        }
    }
    MT_UNPACK()
    if (tid < 32) red[tid] = 0.f;
    __syncthreads();
    float4 bi = *(const float4*)(bias + col0 + tx * 4);
    float ba4[4] = {bi.x, bi.y, bi.z, bi.w};
#pragma unroll
    for (int j = 0; j < 4; j++) {
        float sv = fmaxf(acc[0][j] + ba4[j], 0.f) + fmaxf(acc[1][j] + ba4[j], 0.f) +
                   fmaxf(acc[2][j] + ba4[j], 0.f) + fmaxf(acc[3][j] + ba4[j], 0.f);
        // reduce over the 4 ty-subgroups within the warp (lane bits 3,4)
        sv += __shfl_xor_sync(0xffffffffu, sv, 8);
        sv += __shfl_xor_sync(0xffffffffu, sv, 16);
        if ((tid & 31) < 8) atomicAdd(&red[tx * 4 + j], sv);
    }
    __syncthreads();
    if (tid < 32) atomicAdd(&S[batch * 256 + col0 + tid], red[tid]);
}

// ---------------------------------------------------------------------------
// ah split-K partials: grid 16 (4 batches x 4 k-segments of 64).
// vs = relu(E2a+E2b+be2) at row tgt; accumulates into g_AH.
__global__ void k_ah(const float* __restrict__ x, const float* __restrict__ Wl,
                     const float* __restrict__ be2) {
    __shared__ float vs[64];
    int b = blockIdx.x >> 2, kseg = blockIdx.x & 3;
    int t = threadIdx.x;
    int tgt = (int)x[b * 257 * 40 + 256 * 40];
    if (t < 64) {
        int col = kseg * 64 + t;
        size_t idx = (size_t)(b * 256 + tgt) * 256 + col;
        vs[t] = fmaxf(g_E2[idx] + g_E2[E2_HALF + idx] + be2[col], 0.f);
    }
    __syncthreads();
    float acc = 0.f;
#pragma unroll 8
    for (int k = 0; k < 64; k++)
        acc += vs[k] * Wl[(kseg * 64 + k) * 256 + t];
    atomicAdd(&g_AH[b * 256 + t], acc);
}

// ---------------------------------------------------------------------------
// logits = relu(AH+bl)*Sn; per-head softmax over DIM; head-mean of softmax*Sh;
// 32x8 output GEMM.
__global__ void k_final(const float* __restrict__ bl, const float* __restrict__ Wa,
                        const float* __restrict__ ba, float* __restrict__ out) {
    __shared__ float od[32];
    int b = blockIdx.x, tid = threadIdx.x;
    int h = tid >> 5, d = tid & 31;
    int t = d * 8 + h;                       // (DIM,HEAD) reshape index
    float ahv = fmaxf(g_AH[b * 256 + t] + bl[t], 0.f);
    float logit = ahv * g_Sn[b * 256 + t];
    float m = logit;
#pragma unroll
    for (int o = 16; o > 0; o >>= 1) m = fmaxf(m, __shfl_xor_sync(0xffffffffu, m, o));
    float e = expf(logit - m);
    float ssum = e;
#pragma unroll
    for (int o = 16; o > 0; o >>= 1) ssum += __shfl_xor_sync(0xffffffffu, ssum, o);
    float val = (e / ssum) * g_Sh[b * 256 + t] * 0.125f;
    if (tid < 32) od[tid] = 0.f;
    __syncthreads();
    atomicAdd(&od[d], val);
    __syncthreads();
    if (tid < 8) {
        float acc = ba[tid];
#pragma unroll
        for (int dd = 0; dd < 32; dd++) acc += od[dd] * Wa[dd * 8 + tid];
        out[b * 8 + tid] = acc;
    }
    (void)h;
}

// ---------------------------------------------------------------------------
extern "C" void kernel_launch(void* const* d_in, const int* in_sizes, int n_in,
                              void* d_out, int out_size) {
    const float* x   = (const float*)d_in[0];
    const float* adj = (const float*)d_in[1];
    const float* We1 = (const float*)d_in[2];
    const float* be1 = (const float*)d_in[3];
    const float* We2 = (const float*)d_in[4];
    const float* be2 = (const float*)d_in[5];
    const float* Wl  = (const float*)d_in[6];
    const float* bl  = (const float*)d_in[7];
    const float* Wn  = (const float*)d_in[8];
    const float* bn  = (const float*)d_in[9];
    const float* Wh  = (const float*)d_in[10];
    const float* bh  = (const float*)d_in[11];
    const float* Wa  = (const float*)d_in[12];
    const float* ba  = (const float*)d_in[13];
    float* out = (float*)d_out;

    float* pE1;
    cudaGetSymbolAddress((void**)&pE1, g_E1);

    k_embed1<<<256, 256>>>(x, We1, be1);
    k_gemmE2<<<dim3(8, 16, 2), 128>>>(pE1, We2);       // E2 partials (split-K)
    k_gemmNE<<<dim3(8, 4, 8), 128>>>(adj, be2);        // NE partials (split-K, fused relu)
    k_colsum<<<dim3(8, 16, 2), 128>>>(Wn, bn, Wh, bh); // S_n, S_h
    k_ah<<<16, 256>>>(x, Wl, be2);
    k_final<<<4, 256>>>(bl, Wa, ba, out);

    (void)in_sizes; (void)n_in; (void)out_size;
}